// round 12
// baseline (speedup 1.0000x reference)
#include <cuda_runtime.h>
#include <cooperative_groups.h>
#include <cstdint>

namespace cg = cooperative_groups;

#define NB    4
#define NPTS  16384
#define NC    64
#define NSMP  1024      // S (npoint)
#define NNEI  32        // nsample
#define D0    67        // 3 + C
#define D1    64
#define D2    64
#define D3    128

#define FCTAS 8                 // cluster size
#define FTHR  256               // threads per CTA (uniform)
#define PPC   (NPTS / FCTAS)    // 2048 points per FPS CTA
#define PPT   (PPC / FTHR)      // 8 points per thread

#define NFPS  (NB * FCTAS)      // 32 FPS CTAs (clusters 0..3)
#define NWRK  112               // worker CTAs (clusters 4..17); total 144 <= 148
#define NTASK (NB * NSMP)       // 4096 tasks
#define PUB   8                 // publish cadence (steps)

// centroid staging (byte-identical every launch) + progress flags
__device__ float    g_cent[NB * NSMP * 3];
__device__ unsigned g_prog[NB * 32];   // padded, zero-init, monotone

__device__ __forceinline__ unsigned smem_u32(const void* p) {
    return (unsigned)__cvta_generic_to_shared(p);
}
__device__ __forceinline__ unsigned mapa_u32(unsigned laddr, unsigned rank) {
    unsigned r;
    asm("mapa.shared::cluster.u32 %0, %1, %2;" : "=r"(r) : "r"(laddr), "r"(rank));
    return r;
}
__device__ __forceinline__ void st_cluster_f4(unsigned raddr, float x, float y, float z, float w) {
    asm volatile("st.shared::cluster.v4.f32 [%0], {%1,%2,%3,%4};"
                 :: "r"(raddr), "f"(x), "f"(y), "f"(z), "f"(w) : "memory");
}
__device__ __forceinline__ void st_cluster_u32(unsigned raddr, unsigned v) {
    asm volatile("st.shared::cluster.u32 [%0], %1;" :: "r"(raddr), "r"(v) : "memory");
}
__device__ __forceinline__ unsigned redux_max_u32(unsigned v) {
    unsigned r;
    asm("redux.sync.max.u32 %0, %1, 0xffffffff;" : "=r"(r) : "r"(v));
    return r;
}
__device__ __forceinline__ unsigned redux_min_u32(unsigned v) {
    unsigned r;
    asm("redux.sync.min.u32 %0, %1, 0xffffffff;" : "=r"(r) : "r"(v));
    return r;
}
__device__ __forceinline__ void cluster_arrive() {
    asm volatile("barrier.cluster.arrive.aligned;" ::: "memory");
}
__device__ __forceinline__ void cluster_wait() {
    asm volatile("barrier.cluster.wait.aligned;" ::: "memory");
}
__device__ __forceinline__ unsigned ld_acquire_gpu_u32(const unsigned* p) {
    unsigned v;
    asm volatile("ld.acquire.gpu.global.u32 %0, [%1];" : "=r"(v) : "l"(p) : "memory");
    return v;
}
__device__ __forceinline__ void st_release_gpu_u32(unsigned* p, unsigned v) {
    asm volatile("st.release.gpu.global.u32 [%0], %1;" :: "l"(p), "r"(v) : "memory");
}

// ===========================================================================
// FPS role (R11 math verbatim) — clusters 0..3, coords in dynamic smem.
// Adds: g_cent writes + release-publish of g_prog every PUB steps.
// ===========================================================================
__device__ void fps_role(float* dsm,
                         const float* __restrict__ xyz,
                         float* __restrict__ out_xyz) {
    float* sx = dsm;
    float* sy = dsm + PPC;
    float* sz = dsm + 2 * PPC;
    __shared__ float4 s_rec[2][FCTAS];
    __shared__ unsigned s_lk[2][FCTAS];
    __shared__ unsigned long long s_wkey[FTHR / 32];

    cg::cluster_group cluster = cg::this_cluster();
    const int crank = cluster.block_rank();
    const int b     = blockIdx.x / FCTAS;
    const int tid   = threadIdx.x;
    const int lane  = tid & 31;
    const int wid   = tid >> 5;

    const float* base = xyz + (size_t)b * NPTS * 3;
    const int g0 = crank * PPC;

    for (int k = tid; k < PPC * 3; k += FTHR) {
        float v = base[(size_t)g0 * 3 + k];
        int p = k / 3, c = k - 3 * p;
        if (c == 0)      sx[p] = v;
        else if (c == 1) sy[p] = v;
        else             sz[p] = v;
    }
    cluster.sync();

    float px[PPT], py[PPT], pz[PPT], dist[PPT];
#pragma unroll
    for (int j = 0; j < PPT; j++) {
        int i = tid + j * FTHR;
        px[j] = sx[i]; py[j] = sy[i]; pz[j] = sz[i];
        dist[j] = 3.4e38f;
    }

    unsigned a_rec[2], a_lk[2];
    if (wid == 0 && lane < FCTAS) {
        a_rec[0] = mapa_u32(smem_u32(&s_rec[0][crank]), lane);
        a_rec[1] = mapa_u32(smem_u32(&s_rec[1][crank]), lane);
        a_lk[0]  = mapa_u32(smem_u32(&s_lk[0][crank]),  lane);
        a_lk[1]  = mapa_u32(smem_u32(&s_lk[1][crank]),  lane);
    }

    float cx = base[0], cy = base[1], cz = base[2];
    float* oxy = out_xyz + (size_t)b * NSMP * 3;
    float* gc  = g_cent + (size_t)b * NSMP * 3;

    for (int s = 0; s < NSMP; s++) {
        if (crank == 0 && tid == 0) {
            oxy[s * 3 + 0] = cx; oxy[s * 3 + 1] = cy; oxy[s * 3 + 2] = cz;
            gc[s * 3 + 0] = cx; gc[s * 3 + 1] = cy; gc[s * 3 + 2] = cz;
            if ((s & (PUB - 1)) == (PUB - 1))
                st_release_gpu_u32(&g_prog[b * 32], (unsigned)(s + 1));
        }

        float bv = -1.0f; int bi = 0;
#pragma unroll
        for (int j = 0; j < PPT; j++) {
            float dx = px[j] - cx, dy = py[j] - cy, dz = pz[j] - cz;
            float d  = dx * dx + dy * dy + dz * dz;
            float nd = fminf(dist[j], d);
            dist[j] = nd;
            if (nd > bv) { bv = nd; bi = tid + j * FTHR; }
        }

        unsigned db = __float_as_uint(bv);
        unsigned mx = redux_max_u32(db);
        unsigned gi = (unsigned)(g0 + bi);
        unsigned cand = (db == mx) ? gi : 0xffffffffu;
        unsigned mi = redux_min_u32(cand);
        if (lane == 0)
            s_wkey[wid] = ((unsigned long long)mx << 32) | (0xffffffffu - mi);
        __syncthreads();

        const int par = s & 1;
        if (wid == 0) {
            unsigned long long k = s_wkey[0];
#pragma unroll
            for (int w = 1; w < FTHR / 32; w++) {
                unsigned long long t = s_wkey[w];
                if (t > k) k = t;
            }
            if (lane < FCTAS) {
                unsigned g  = 0xffffffffu - (unsigned)k;
                int li = (int)g - g0;
                st_cluster_f4(a_rec[par], sx[li], sy[li], sz[li],
                              __uint_as_float((unsigned)(k >> 32)));
                st_cluster_u32(a_lk[par], (unsigned)k);
            }
        }
        cluster_arrive();
        cluster_wait();

        {
            unsigned long long km = 0ull;
            float X = 0.f, Y = 0.f, Z = 0.f;
#pragma unroll
            for (int r = 0; r < FCTAS; r++) {
                float4 rec = s_rec[par][r];
                unsigned lk = s_lk[par][r];
                unsigned long long ck =
                    ((unsigned long long)__float_as_uint(rec.w) << 32) | lk;
                if (ck > km) { km = ck; X = rec.x; Y = rec.y; Z = rec.z; }
            }
            cx = X; cy = Y; cz = Z;
        }
    }
}

// ===========================================================================
// Worker role — private SM, all weights staged once, ~37 tasks per CTA.
// Per task: gate on g_prog (tid0 polls, rest parked), ball query (warp 0,
// pipelined), fused MLP + maxpool (R11 math verbatim).
// ===========================================================================
__device__ void worker_role(float* sm,
                            const float* __restrict__ xyz,
                            const float* __restrict__ feat,
                            const float* __restrict__ W0, const float* __restrict__ b0,
                            const float* __restrict__ W1, const float* __restrict__ b1,
                            const float* __restrict__ W2, const float* __restrict__ b2,
                            float* __restrict__ out_feat) {
    float* W0s = sm;               // 4288
    float* W1s = W0s + D0 * D1;    // 4096
    float* W2s = W1s + D1 * D2;    // 8192
    float* b0s = W2s + D2 * D3;    // 64
    float* b1s = b0s + D1;         // 64
    float* b2s = b1s + D2;         // 128
    float* hA  = b2s + D3;         // 2144
    float* hB  = hA + NNEI * D0;   // 4096
    float* hC  = hB + NNEI * D3;   // 2048
    __shared__ int   s_ni[NNEI];
    __shared__ float s_c[3];

    const int wk  = blockIdx.x - NFPS;
    const int tid = threadIdx.x;
    const int lane = tid & 31;
    const int wid  = tid >> 5;
    const int chq = tid & 15;
    const int ns0 = (tid >> 4) * 2;

    // stage ALL weights + biases once
    for (int i = tid; i < D0 * D1; i += FTHR) W0s[i] = W0[i];
    for (int i = tid; i < D1 * D2; i += FTHR) W1s[i] = W1[i];
    for (int i = tid; i < D2 * D3; i += FTHR) W2s[i] = W2[i];
    if (tid < D1) b0s[tid] = b0[tid];
    if (tid < D2) b1s[tid] = b1[tid];
    if (tid < D3) b2s[tid] = b2[tid];
    __syncthreads();

    for (int t = wk; t < NTASK; t += NWRK) {
        const int b   = t & 3;
        const int s   = t >> 2;
        const int cid = b * NSMP + s;

        if (tid == 0) {
            while (ld_acquire_gpu_u32(&g_prog[b * 32]) < (unsigned)(s + 1))
                __nanosleep(1000);
            const float* gc = g_cent + ((size_t)b * NSMP + s) * 3;
            s_c[0] = __ldcg(gc + 0);
            s_c[1] = __ldcg(gc + 1);
            s_c[2] = __ldcg(gc + 2);
        }
        __syncthreads();

        const float cx = s_c[0], cy = s_c[1], cz = s_c[2];
        const float* xb = xyz  + (size_t)b * NPTS * 3;
        const float* fb = feat + (size_t)b * NPTS * NC;

        // ---- ball query (warp 0, 128-pt pipelined chunks) ----
        if (wid == 0) {
            const float r2 = 0.2f * 0.2f;
            int cnt = 0, first = 0;
            for (int j0 = 0; j0 < NPTS && cnt < NNEI; j0 += 128) {
                float d2v[4];
#pragma unroll
                for (int c = 0; c < 4; c++) {
                    const int j = j0 + c * 32 + lane;
                    float dx = xb[3 * j]     - cx;
                    float dy = xb[3 * j + 1] - cy;
                    float dz = xb[3 * j + 2] - cz;
                    d2v[c] = dx * dx + dy * dy + dz * dz;
                }
#pragma unroll
                for (int c = 0; c < 4; c++) {
                    bool hit = (d2v[c] <= r2);
                    unsigned m = __ballot_sync(0xffffffffu, hit);
                    if (m) {
                        if (cnt == 0) first = j0 + c * 32 + (__ffs(m) - 1);
                        int pos = cnt + __popc(m & ((1u << lane) - 1u));
                        if (hit && pos < NNEI) s_ni[pos] = j0 + c * 32 + lane;
                        cnt += __popc(m);
                    }
                }
            }
            if (cnt < NNEI) {
                for (int p = cnt + lane; p < NNEI; p += 32) s_ni[p] = first;
            }
        }
        __syncthreads();

        // ---- build h0 = [g_xyz - centroid, g_feat] ----
        for (int e = tid; e < NNEI * 3; e += FTHR) {
            int ns = e / 3, k = e - 3 * ns;
            float c = (k == 0) ? cx : ((k == 1) ? cy : cz);
            hA[ns * D0 + k] = xb[(size_t)s_ni[ns] * 3 + k] - c;
        }
        for (int e = tid; e < NNEI * NC; e += FTHR) {
            int ns = e >> 6, c = e & 63;
            hA[ns * D0 + 3 + c] = fb[(size_t)s_ni[ns] * NC + c];
        }
        __syncthreads();

        // ---- layer 1 ----
        {
            float4 bs = *(float4*)&b0s[chq * 4];
            float a00 = bs.x, a01 = bs.y, a02 = bs.z, a03 = bs.w;
            float a10 = bs.x, a11 = bs.y, a12 = bs.z, a13 = bs.w;
            const float* h0 = hA + ns0 * D0;
            const float* h1 = hA + (ns0 + 1) * D0;
#pragma unroll 4
            for (int d = 0; d < D0; d++) {
                float v0 = h0[d], v1 = h1[d];
                float4 w = *(float4*)&W0s[d * D1 + chq * 4];
                a00 = fmaf(v0, w.x, a00); a01 = fmaf(v0, w.y, a01);
                a02 = fmaf(v0, w.z, a02); a03 = fmaf(v0, w.w, a03);
                a10 = fmaf(v1, w.x, a10); a11 = fmaf(v1, w.y, a11);
                a12 = fmaf(v1, w.z, a12); a13 = fmaf(v1, w.w, a13);
            }
            *(float4*)&hB[ns0 * D1 + chq * 4] =
                make_float4(fmaxf(a00, 0.f), fmaxf(a01, 0.f), fmaxf(a02, 0.f), fmaxf(a03, 0.f));
            *(float4*)&hB[(ns0 + 1) * D1 + chq * 4] =
                make_float4(fmaxf(a10, 0.f), fmaxf(a11, 0.f), fmaxf(a12, 0.f), fmaxf(a13, 0.f));
        }
        __syncthreads();

        // ---- layer 2 ----
        {
            float4 bs = *(float4*)&b1s[chq * 4];
            float a00 = bs.x, a01 = bs.y, a02 = bs.z, a03 = bs.w;
            float a10 = bs.x, a11 = bs.y, a12 = bs.z, a13 = bs.w;
            const float* h0 = hB + ns0 * D1;
            const float* h1 = hB + (ns0 + 1) * D1;
#pragma unroll 4
            for (int d = 0; d < D1; d++) {
                float v0 = h0[d], v1 = h1[d];
                float4 w = *(float4*)&W1s[d * D2 + chq * 4];
                a00 = fmaf(v0, w.x, a00); a01 = fmaf(v0, w.y, a01);
                a02 = fmaf(v0, w.z, a02); a03 = fmaf(v0, w.w, a03);
                a10 = fmaf(v1, w.x, a10); a11 = fmaf(v1, w.y, a11);
                a12 = fmaf(v1, w.z, a12); a13 = fmaf(v1, w.w, a13);
            }
            *(float4*)&hC[ns0 * D2 + chq * 4] =
                make_float4(fmaxf(a00, 0.f), fmaxf(a01, 0.f), fmaxf(a02, 0.f), fmaxf(a03, 0.f));
            *(float4*)&hC[(ns0 + 1) * D2 + chq * 4] =
                make_float4(fmaxf(a10, 0.f), fmaxf(a11, 0.f), fmaxf(a12, 0.f), fmaxf(a13, 0.f));
        }
        __syncthreads();

        // ---- layer 3 ----
        {
            const int ch8 = chq * 8;
            float4 bs0 = *(float4*)&b2s[ch8];
            float4 bs1 = *(float4*)&b2s[ch8 + 4];
            float a0[8] = {bs0.x, bs0.y, bs0.z, bs0.w, bs1.x, bs1.y, bs1.z, bs1.w};
            float a1[8] = {bs0.x, bs0.y, bs0.z, bs0.w, bs1.x, bs1.y, bs1.z, bs1.w};
            const float* h0 = hC + ns0 * D2;
            const float* h1 = hC + (ns0 + 1) * D2;
#pragma unroll 4
            for (int d = 0; d < D2; d++) {
                float v0 = h0[d], v1 = h1[d];
                float4 w0 = *(float4*)&W2s[d * D3 + ch8];
                float4 w1 = *(float4*)&W2s[d * D3 + ch8 + 4];
                a0[0] = fmaf(v0, w0.x, a0[0]); a0[1] = fmaf(v0, w0.y, a0[1]);
                a0[2] = fmaf(v0, w0.z, a0[2]); a0[3] = fmaf(v0, w0.w, a0[3]);
                a0[4] = fmaf(v0, w1.x, a0[4]); a0[5] = fmaf(v0, w1.y, a0[5]);
                a0[6] = fmaf(v0, w1.z, a0[6]); a0[7] = fmaf(v0, w1.w, a0[7]);
                a1[0] = fmaf(v1, w0.x, a1[0]); a1[1] = fmaf(v1, w0.y, a1[1]);
                a1[2] = fmaf(v1, w0.z, a1[2]); a1[3] = fmaf(v1, w0.w, a1[3]);
                a1[4] = fmaf(v1, w1.x, a1[4]); a1[5] = fmaf(v1, w1.y, a1[5]);
                a1[6] = fmaf(v1, w1.z, a1[6]); a1[7] = fmaf(v1, w1.w, a1[7]);
            }
            *(float4*)&hB[ns0 * D3 + ch8] =
                make_float4(fmaxf(a0[0], 0.f), fmaxf(a0[1], 0.f), fmaxf(a0[2], 0.f), fmaxf(a0[3], 0.f));
            *(float4*)&hB[ns0 * D3 + ch8 + 4] =
                make_float4(fmaxf(a0[4], 0.f), fmaxf(a0[5], 0.f), fmaxf(a0[6], 0.f), fmaxf(a0[7], 0.f));
            *(float4*)&hB[(ns0 + 1) * D3 + ch8] =
                make_float4(fmaxf(a1[0], 0.f), fmaxf(a1[1], 0.f), fmaxf(a1[2], 0.f), fmaxf(a1[3], 0.f));
            *(float4*)&hB[(ns0 + 1) * D3 + ch8 + 4] =
                make_float4(fmaxf(a1[4], 0.f), fmaxf(a1[5], 0.f), fmaxf(a1[6], 0.f), fmaxf(a1[7], 0.f));
        }
        __syncthreads();

        // ---- maxpool ----
        for (int dj = tid; dj < D3; dj += FTHR) {
            float m = hB[dj];
#pragma unroll 4
            for (int ns = 1; ns < NNEI; ns++) m = fmaxf(m, hB[ns * D3 + dj]);
            out_feat[(size_t)cid * D3 + dj] = m;
        }
        __syncthreads();
    }
}

// ===========================================================================
__global__ __launch_bounds__(FTHR, 1) __cluster_dims__(FCTAS, 1, 1)
void sa_module_kernel(const float* __restrict__ xyz,
                      const float* __restrict__ feat,
                      const float* __restrict__ W0, const float* __restrict__ b0,
                      const float* __restrict__ W1, const float* __restrict__ b1,
                      const float* __restrict__ W2, const float* __restrict__ b2,
                      float* __restrict__ out_xyz,
                      float* __restrict__ out_feat) {
    extern __shared__ float dsm[];
    if (blockIdx.x < NFPS) {
        fps_role(dsm, xyz, out_xyz);
    } else {
        worker_role(dsm, xyz, feat, W0, b0, W1, b1, W2, b2, out_feat);
    }
}

// ---------------------------------------------------------------------------
extern "C" void kernel_launch(void* const* d_in, const int* in_sizes, int n_in,
                              void* d_out, int out_size) {
    const float* xyz  = (const float*)d_in[0];
    const float* feat = (const float*)d_in[1];
    const float* W0   = (const float*)d_in[2];
    const float* b0   = (const float*)d_in[3];
    const float* W1   = (const float*)d_in[4];
    const float* b1   = (const float*)d_in[5];
    const float* W2   = (const float*)d_in[6];
    const float* b2   = (const float*)d_in[7];

    float* out      = (float*)d_out;
    float* new_xyz  = out;                       // B*S*3
    float* out_feat = out + NB * NSMP * 3;       // B*S*128

    // dynamic smem = max(worker 100480, fps 24576) -> forces occupancy 1
    const int smem = (D0*D1 + D1*D2 + D2*D3 + D1 + D2 + D3
                      + NNEI*D0 + NNEI*D3 + NNEI*D2) * 4;   // 100480 B
    cudaFuncSetAttribute(sa_module_kernel,
                         cudaFuncAttributeMaxDynamicSharedMemorySize, smem);

    sa_module_kernel<<<NFPS + NWRK, FTHR, smem>>>(
        xyz, feat, W0, b0, W1, b1, W2, b2, new_xyz, out_feat);
}

// round 13
// speedup vs baseline: 1.2092x; 1.2092x over previous
#include <cuda_runtime.h>
#include <cooperative_groups.h>
#include <cstdint>

namespace cg = cooperative_groups;

#define NB    4
#define NPTS  16384
#define NC    64
#define NSMP  1024      // S (npoint)
#define NNEI  32        // nsample
#define D0    67        // 3 + C
#define D1    64
#define D2    64
#define D3    128

#define FCTAS 4                 // cluster size (CTAs per batch)
#define FTHR  512               // threads per FPS CTA
#define PPC   (NPTS / FCTAS)    // 4096 points per CTA
#define PPT   (PPC / FTHR)      // 8 points per thread
#define NWARP (FTHR / 32)       // 16 warps

#define NTASK (NB * NSMP)       // 4096 centroid tasks
#define MLPC  296               // persistent MLP CTAs (2 per SM x 148)

// scratch: ball query neighbor indices
__device__ int g_ball_idx[NB * NSMP * NNEI];

__device__ __forceinline__ unsigned smem_u32(const void* p) {
    return (unsigned)__cvta_generic_to_shared(p);
}
__device__ __forceinline__ unsigned mapa_u32(unsigned laddr, unsigned rank) {
    unsigned r;
    asm("mapa.shared::cluster.u32 %0, %1, %2;" : "=r"(r) : "r"(laddr), "r"(rank));
    return r;
}
__device__ __forceinline__ void st_cluster_f4(unsigned raddr, float x, float y, float z, float w) {
    asm volatile("st.shared::cluster.v4.f32 [%0], {%1,%2,%3,%4};"
                 :: "r"(raddr), "f"(x), "f"(y), "f"(z), "f"(w) : "memory");
}
__device__ __forceinline__ void st_cluster_u32(unsigned raddr, unsigned v) {
    asm volatile("st.shared::cluster.u32 [%0], %1;" :: "r"(raddr), "r"(v) : "memory");
}
__device__ __forceinline__ unsigned redux_max_u32(unsigned v) {
    unsigned r;
    asm("redux.sync.max.u32 %0, %1, 0xffffffff;" : "=r"(r) : "r"(v));
    return r;
}
__device__ __forceinline__ unsigned redux_min_u32(unsigned v) {
    unsigned r;
    asm("redux.sync.min.u32 %0, %1, 0xffffffff;" : "=r"(r) : "r"(v));
    return r;
}
__device__ __forceinline__ void cluster_arrive() {
    asm volatile("barrier.cluster.arrive.aligned;" ::: "memory");
}
__device__ __forceinline__ void cluster_wait() {
    asm volatile("barrier.cluster.wait.aligned;" ::: "memory");
}

// ---------------------------------------------------------------------------
// FPS: one 4-CTA cluster per batch, 512 thr/CTA, 8 register-resident pts/thr.
// Same packed-key selection as the proven kernel (global keys -> partition-
// invariant winners). Stage 2 = lane-parallel 16-key load + 2x redux.
// ---------------------------------------------------------------------------
__global__ __launch_bounds__(FTHR, 1) __cluster_dims__(FCTAS, 1, 1)
void fps_cluster_kernel(const float* __restrict__ xyz, float* __restrict__ out_xyz) {
    extern __shared__ float dsm[];
    float* sx = dsm;
    float* sy = dsm + PPC;
    float* sz = dsm + 2 * PPC;
    __shared__ float4 s_rec[2][FCTAS];
    __shared__ unsigned s_lk[2][FCTAS];
    __shared__ unsigned long long s_wkey[NWARP];

    cg::cluster_group cluster = cg::this_cluster();
    const int crank = cluster.block_rank();
    const int b     = blockIdx.x / FCTAS;
    const int tid   = threadIdx.x;
    const int lane  = tid & 31;
    const int wid   = tid >> 5;

    const float* base = xyz + (size_t)b * NPTS * 3;
    const int g0 = crank * PPC;

    for (int k = tid; k < PPC * 3; k += FTHR) {
        float v = base[(size_t)g0 * 3 + k];
        int p = k / 3, c = k - 3 * p;
        if (c == 0)      sx[p] = v;
        else if (c == 1) sy[p] = v;
        else             sz[p] = v;
    }
    cluster.sync();

    float px[PPT], py[PPT], pz[PPT], dist[PPT];
#pragma unroll
    for (int j = 0; j < PPT; j++) {
        int i = tid + j * FTHR;
        px[j] = sx[i]; py[j] = sy[i]; pz[j] = sz[i];
        dist[j] = 3.4e38f;
    }

    unsigned a_rec[2], a_lk[2];
    if (wid == 0 && lane < FCTAS) {
        a_rec[0] = mapa_u32(smem_u32(&s_rec[0][crank]), lane);
        a_rec[1] = mapa_u32(smem_u32(&s_rec[1][crank]), lane);
        a_lk[0]  = mapa_u32(smem_u32(&s_lk[0][crank]),  lane);
        a_lk[1]  = mapa_u32(smem_u32(&s_lk[1][crank]),  lane);
    }

    float cx = base[0], cy = base[1], cz = base[2];
    float* oxy = out_xyz + (size_t)b * NSMP * 3;

    for (int s = 0; s < NSMP; s++) {
        if (crank == 0 && tid == 0) {
            oxy[s * 3 + 0] = cx; oxy[s * 3 + 1] = cy; oxy[s * 3 + 2] = cz;
        }

        // update + thread argmax (ascending local idx -> first max kept)
        float bv = -1.0f; int bi = 0;
#pragma unroll
        for (int j = 0; j < PPT; j++) {
            float dx = px[j] - cx, dy = py[j] - cy, dz = pz[j] - cz;
            float d  = dx * dx + dy * dy + dz * dz;
            float nd = fminf(dist[j], d);
            dist[j] = nd;
            if (nd > bv) { bv = nd; bi = tid + j * FTHR; }
        }

        // warp argmax via redux: max dist-bits, then min global idx among ties
        unsigned db = __float_as_uint(bv);
        unsigned mx = redux_max_u32(db);
        unsigned gi = (unsigned)(g0 + bi);
        unsigned cand = (db == mx) ? gi : 0xffffffffu;
        unsigned mi = redux_min_u32(cand);
        if (lane == 0)
            s_wkey[wid] = ((unsigned long long)mx << 32) | (0xffffffffu - mi);
        __syncthreads();

        const int par = s & 1;
        if (wid == 0) {
            // CTA argmax: lane-parallel load of 16 warp keys + 2x redux
            unsigned long long wk = (lane < NWARP) ? s_wkey[lane] : 0ull;
            unsigned hi2 = (unsigned)(wk >> 32);
            unsigned mx2 = redux_max_u32(hi2);
            unsigned cand2 = (hi2 == mx2) ? (unsigned)wk : 0u;  // lo = ~idx
            unsigned lo2 = redux_max_u32(cand2);                // max lo = min idx
            if (lane < FCTAS) {
                unsigned g  = 0xffffffffu - lo2;
                int li = (int)g - g0;                           // CTA-local winner
                st_cluster_f4(a_rec[par], sx[li], sy[li], sz[li],
                              __uint_as_float(mx2));
                st_cluster_u32(a_lk[par], lo2);
            }
        }
        cluster_arrive();
        cluster_wait();

        // all threads serially reduce the 4 records (deterministic winner)
        {
            unsigned long long km = 0ull;
            float X = 0.f, Y = 0.f, Z = 0.f;
#pragma unroll
            for (int r = 0; r < FCTAS; r++) {
                float4 rec = s_rec[par][r];
                unsigned lk = s_lk[par][r];
                unsigned long long ck =
                    ((unsigned long long)__float_as_uint(rec.w) << 32) | lk;
                if (ck > km) { km = ck; X = rec.x; Y = rec.y; Z = rec.z; }
            }
            cx = X; cy = Y; cz = Z;
        }
    }
}

// ---------------------------------------------------------------------------
// Ball query: one warp per centroid, 128-point chunks (loads batched ahead of
// ballots -> 4x latency amortization). Append order identical to serial scan.
// ---------------------------------------------------------------------------
__global__ void ball_kernel(const float* __restrict__ xyz,
                            const float* __restrict__ new_xyz) {
    const int gw   = (blockIdx.x * blockDim.x + threadIdx.x) >> 5;
    const int lane = threadIdx.x & 31;
    if (gw >= NB * NSMP) return;
    const int b = gw >> 10;
    const float* base = xyz + (size_t)b * NPTS * 3;
    const float cx = new_xyz[gw * 3 + 0];
    const float cy = new_xyz[gw * 3 + 1];
    const float cz = new_xyz[gw * 3 + 2];
    const float r2 = 0.2f * 0.2f;
    int* out = g_ball_idx + gw * NNEI;

    int cnt = 0, first = 0;
    for (int j0 = 0; j0 < NPTS && cnt < NNEI; j0 += 128) {
        float d2v[4];
#pragma unroll
        for (int c = 0; c < 4; c++) {
            const int j = j0 + c * 32 + lane;
            float dx = base[3 * j]     - cx;
            float dy = base[3 * j + 1] - cy;
            float dz = base[3 * j + 2] - cz;
            d2v[c] = dx * dx + dy * dy + dz * dz;
        }
#pragma unroll
        for (int c = 0; c < 4; c++) {
            bool hit = (d2v[c] <= r2);
            unsigned m = __ballot_sync(0xffffffffu, hit);
            if (m) {
                if (cnt == 0) first = j0 + c * 32 + (__ffs(m) - 1);
                int pos = cnt + __popc(m & ((1u << lane) - 1u));
                if (hit && pos < NNEI) out[pos] = j0 + c * 32 + lane;
                cnt += __popc(m);
            }
        }
    }
    if (cnt < NNEI) {
        for (int p = cnt + lane; p < NNEI; p += 32) out[p] = first;
    }
}

// ---------------------------------------------------------------------------
// Persistent MLP: 296 CTAs, ALL weights staged in smem once, ~14 tasks each.
// (R11, proven.)
// ---------------------------------------------------------------------------
__global__ __launch_bounds__(256, 2)
void group_mlp_kernel(const float* __restrict__ xyz,
                      const float* __restrict__ feat,
                      const float* __restrict__ W0, const float* __restrict__ b0,
                      const float* __restrict__ W1, const float* __restrict__ b1,
                      const float* __restrict__ W2, const float* __restrict__ b2,
                      const float* __restrict__ new_xyz,
                      float* __restrict__ out_feat) {
    extern __shared__ float sm[];
    float* W0s = sm;               // 4288
    float* W1s = W0s + D0 * D1;    // 4096
    float* W2s = W1s + D1 * D2;    // 8192
    float* b0s = W2s + D2 * D3;    // 64
    float* b1s = b0s + D1;         // 64
    float* b2s = b1s + D2;         // 128
    float* hA  = b2s + D3;         // 2144
    float* hB  = hA + NNEI * D0;   // 4096
    float* hC  = hB + NNEI * D3;   // 2048

    const int tid = threadIdx.x;
    const int chq = tid & 15;
    const int ns0 = (tid >> 4) * 2;

    for (int i = tid; i < D0 * D1; i += 256) W0s[i] = W0[i];
    for (int i = tid; i < D1 * D2; i += 256) W1s[i] = W1[i];
    for (int i = tid; i < D2 * D3; i += 256) W2s[i] = W2[i];
    if (tid < D1) b0s[tid] = b0[tid];
    if (tid < D2) b1s[tid] = b1[tid];
    if (tid < D3) b2s[tid] = b2[tid];
    __syncthreads();

    for (int cid = blockIdx.x; cid < NTASK; cid += MLPC) {
        const int b = cid >> 10;
        const float* xb = xyz  + (size_t)b * NPTS * 3;
        const float* fb = feat + (size_t)b * NPTS * NC;
        const int* ni = g_ball_idx + cid * NNEI;

        for (int e = tid; e < NNEI * 3; e += 256) {
            int ns = e / 3, k = e - 3 * ns;
            hA[ns * D0 + k] = xb[(size_t)__ldg(ni + ns) * 3 + k]
                              - new_xyz[cid * 3 + k];
        }
        for (int e = tid; e < NNEI * NC; e += 256) {
            int ns = e >> 6, c = e & 63;
            hA[ns * D0 + 3 + c] = fb[(size_t)__ldg(ni + ns) * NC + c];
        }
        __syncthreads();

        // ---- layer 1 ----
        {
            float4 bs = *(float4*)&b0s[chq * 4];
            float a00 = bs.x, a01 = bs.y, a02 = bs.z, a03 = bs.w;
            float a10 = bs.x, a11 = bs.y, a12 = bs.z, a13 = bs.w;
            const float* h0 = hA + ns0 * D0;
            const float* h1 = hA + (ns0 + 1) * D0;
#pragma unroll 4
            for (int d = 0; d < D0; d++) {
                float v0 = h0[d], v1 = h1[d];
                float4 w = *(float4*)&W0s[d * D1 + chq * 4];
                a00 = fmaf(v0, w.x, a00); a01 = fmaf(v0, w.y, a01);
                a02 = fmaf(v0, w.z, a02); a03 = fmaf(v0, w.w, a03);
                a10 = fmaf(v1, w.x, a10); a11 = fmaf(v1, w.y, a11);
                a12 = fmaf(v1, w.z, a12); a13 = fmaf(v1, w.w, a13);
            }
            *(float4*)&hB[ns0 * D1 + chq * 4] =
                make_float4(fmaxf(a00, 0.f), fmaxf(a01, 0.f), fmaxf(a02, 0.f), fmaxf(a03, 0.f));
            *(float4*)&hB[(ns0 + 1) * D1 + chq * 4] =
                make_float4(fmaxf(a10, 0.f), fmaxf(a11, 0.f), fmaxf(a12, 0.f), fmaxf(a13, 0.f));
        }
        __syncthreads();

        // ---- layer 2 ----
        {
            float4 bs = *(float4*)&b1s[chq * 4];
            float a00 = bs.x, a01 = bs.y, a02 = bs.z, a03 = bs.w;
            float a10 = bs.x, a11 = bs.y, a12 = bs.z, a13 = bs.w;
            const float* h0 = hB + ns0 * D1;
            const float* h1 = hB + (ns0 + 1) * D1;
#pragma unroll 4
            for (int d = 0; d < D1; d++) {
                float v0 = h0[d], v1 = h1[d];
                float4 w = *(float4*)&W1s[d * D2 + chq * 4];
                a00 = fmaf(v0, w.x, a00); a01 = fmaf(v0, w.y, a01);
                a02 = fmaf(v0, w.z, a02); a03 = fmaf(v0, w.w, a03);
                a10 = fmaf(v1, w.x, a10); a11 = fmaf(v1, w.y, a11);
                a12 = fmaf(v1, w.z, a12); a13 = fmaf(v1, w.w, a13);
            }
            *(float4*)&hC[ns0 * D2 + chq * 4] =
                make_float4(fmaxf(a00, 0.f), fmaxf(a01, 0.f), fmaxf(a02, 0.f), fmaxf(a03, 0.f));
            *(float4*)&hC[(ns0 + 1) * D2 + chq * 4] =
                make_float4(fmaxf(a10, 0.f), fmaxf(a11, 0.f), fmaxf(a12, 0.f), fmaxf(a13, 0.f));
        }
        __syncthreads();

        // ---- layer 3 ----
        {
            const int ch8 = chq * 8;
            float4 bs0 = *(float4*)&b2s[ch8];
            float4 bs1 = *(float4*)&b2s[ch8 + 4];
            float a0[8] = {bs0.x, bs0.y, bs0.z, bs0.w, bs1.x, bs1.y, bs1.z, bs1.w};
            float a1[8] = {bs0.x, bs0.y, bs0.z, bs0.w, bs1.x, bs1.y, bs1.z, bs1.w};
            const float* h0 = hC + ns0 * D2;
            const float* h1 = hC + (ns0 + 1) * D2;
#pragma unroll 4
            for (int d = 0; d < D2; d++) {
                float v0 = h0[d], v1 = h1[d];
                float4 w0 = *(float4*)&W2s[d * D3 + ch8];
                float4 w1 = *(float4*)&W2s[d * D3 + ch8 + 4];
                a0[0] = fmaf(v0, w0.x, a0[0]); a0[1] = fmaf(v0, w0.y, a0[1]);
                a0[2] = fmaf(v0, w0.z, a0[2]); a0[3] = fmaf(v0, w0.w, a0[3]);
                a0[4] = fmaf(v0, w1.x, a0[4]); a0[5] = fmaf(v0, w1.y, a0[5]);
                a0[6] = fmaf(v0, w1.z, a0[6]); a0[7] = fmaf(v0, w1.w, a0[7]);
                a1[0] = fmaf(v1, w0.x, a1[0]); a1[1] = fmaf(v1, w0.y, a1[1]);
                a1[2] = fmaf(v1, w0.z, a1[2]); a1[3] = fmaf(v1, w0.w, a1[3]);
                a1[4] = fmaf(v1, w1.x, a1[4]); a1[5] = fmaf(v1, w1.y, a1[5]);
                a1[6] = fmaf(v1, w1.z, a1[6]); a1[7] = fmaf(v1, w1.w, a1[7]);
            }
            *(float4*)&hB[ns0 * D3 + ch8] =
                make_float4(fmaxf(a0[0], 0.f), fmaxf(a0[1], 0.f), fmaxf(a0[2], 0.f), fmaxf(a0[3], 0.f));
            *(float4*)&hB[ns0 * D3 + ch8 + 4] =
                make_float4(fmaxf(a0[4], 0.f), fmaxf(a0[5], 0.f), fmaxf(a0[6], 0.f), fmaxf(a0[7], 0.f));
            *(float4*)&hB[(ns0 + 1) * D3 + ch8] =
                make_float4(fmaxf(a1[0], 0.f), fmaxf(a1[1], 0.f), fmaxf(a1[2], 0.f), fmaxf(a1[3], 0.f));
            *(float4*)&hB[(ns0 + 1) * D3 + ch8 + 4] =
                make_float4(fmaxf(a1[4], 0.f), fmaxf(a1[5], 0.f), fmaxf(a1[6], 0.f), fmaxf(a1[7], 0.f));
        }
        __syncthreads();

        for (int dj = tid; dj < D3; dj += 256) {
            float m = hB[dj];
#pragma unroll 4
            for (int ns = 1; ns < NNEI; ns++) m = fmaxf(m, hB[ns * D3 + dj]);
            out_feat[(size_t)cid * D3 + dj] = m;
        }
        __syncthreads();
    }
}

// ---------------------------------------------------------------------------
extern "C" void kernel_launch(void* const* d_in, const int* in_sizes, int n_in,
                              void* d_out, int out_size) {
    const float* xyz  = (const float*)d_in[0];
    const float* feat = (const float*)d_in[1];
    const float* W0   = (const float*)d_in[2];
    const float* b0   = (const float*)d_in[3];
    const float* W1   = (const float*)d_in[4];
    const float* b1   = (const float*)d_in[5];
    const float* W2   = (const float*)d_in[6];
    const float* b2   = (const float*)d_in[7];

    float* out      = (float*)d_out;
    float* new_xyz  = out;                       // B*S*3
    float* out_feat = out + NB * NSMP * 3;       // B*S*128

    const int fps_smem = PPC * 3 * sizeof(float);               // 49152 B
    const int mlp_smem = (D0*D1 + D1*D2 + D2*D3 + D1 + D2 + D3
                          + NNEI*D0 + NNEI*D3 + NNEI*D2) * 4;   // 100480 B
    cudaFuncSetAttribute(fps_cluster_kernel,
                         cudaFuncAttributeMaxDynamicSharedMemorySize, fps_smem);
    cudaFuncSetAttribute(group_mlp_kernel,
                         cudaFuncAttributeMaxDynamicSharedMemorySize, mlp_smem);

    fps_cluster_kernel<<<NB * FCTAS, FTHR, fps_smem>>>(xyz, new_xyz);

    const int bq_threads = 256;
    const int bq_blocks  = (NB * NSMP * 32 + bq_threads - 1) / bq_threads;
    ball_kernel<<<bq_blocks, bq_threads>>>(xyz, new_xyz);

    group_mlp_kernel<<<MLPC, 256, mlp_smem>>>(
        xyz, feat, W0, b0, W1, b1, W2, b2, new_xyz, out_feat);
}